// round 14
// baseline (speedup 1.0000x reference)
#include <cuda_runtime.h>
#include <cuda_bf16.h>
#include <math.h>

#define NPTS 32768
#define NB 16
#define WSTRIDE 4560

typedef unsigned long long u64;
typedef unsigned int u32;

// ---------------- scratch ----------------------------------------------------
__device__ float g_W[NB * WSTRIDE];
__device__ float g_enc[NPTS * 64];
__device__ float g_g[NB * NPTS * 30];

// ---------------- packed f32x2 helpers ---------------------------------------
__device__ __forceinline__ u64 pk2(float lo, float hi) {
    u64 r; asm("mov.b64 %0,{%1,%2};" : "=l"(r) : "f"(lo), "f"(hi)); return r;
}
__device__ __forceinline__ float2 up2(u64 v) {
    float2 r; asm("mov.b64 {%0,%1},%2;" : "=f"(r.x), "=f"(r.y) : "l"(v)); return r;
}
__device__ __forceinline__ u64 fma2(u64 a, u64 b, u64 c) {
    u64 r; asm("fma.rn.f32x2 %0,%1,%2,%3;" : "=l"(r) : "l"(a), "l"(b), "l"(c));
    return r;
}

// ---------------- misc -------------------------------------------------------
__device__ __forceinline__ float silu_f(float z) {
    float e = __expf(-z);
    return __fdividef(z, 1.0f + e);
}
__device__ __forceinline__ float sin_cw(float x) {
    float kf = rintf(x * 0.63661977236758138f);
    float r = fmaf(kf, -1.57079637e+00f, x);
    r = fmaf(kf, 4.37113883e-08f, r);
    r = fmaf(kf, 1.71512489e-15f, r);
    int q = (int)kf;
    float s2 = r * r;
    float ps = fmaf(s2, 2.7525562e-6f, -1.9840874e-4f);
    ps = fmaf(s2, ps, 8.3333310e-3f);
    ps = fmaf(s2, ps, -1.6666667e-1f);
    float sinv = fmaf(r * s2, ps, r);
    float pc = fmaf(s2, 2.4433157e-5f, -1.3888378e-3f);
    pc = fmaf(s2, pc, 4.1666638e-2f);
    pc = fmaf(s2, pc, -0.5f);
    float cosv = fmaf(s2, pc, 1.0f);
    float res = (q & 1) ? cosv : sinv;
    if (q & 2) res = -res;
    return res;
}
__device__ __forceinline__ u32 pack_bf2(float lo, float hi) {
    __nv_bfloat162 t = __floats2bfloat162_rn(lo, hi);
    return *(u32*)&t;
}
__device__ __forceinline__ u32 smem_u32(const void* p) {
    u32 a;
    asm("{ .reg .u64 t; cvta.to.shared.u64 t, %1; cvt.u32.u64 %0, t; }"
        : "=r"(a) : "l"(p));
    return a;
}

// mma.sync m16n8k16 bf16 (baseline PTX, works on plain sm_100)
__device__ __forceinline__ void mma16816(float c[4], const u32 a[4], const u32* b) {
    asm volatile(
        "mma.sync.aligned.m16n8k16.row.col.f32.bf16.bf16.f32 "
        "{%0,%1,%2,%3},{%4,%5,%6,%7},{%8,%9},{%0,%1,%2,%3};"
        : "+f"(c[0]), "+f"(c[1]), "+f"(c[2]), "+f"(c[3])
        : "r"(a[0]), "r"(a[1]), "r"(a[2]), "r"(a[3]), "r"(b[0]), "r"(b[1]));
}
// ldmatrix x4 (baseline PTX, sm_75+)
__device__ __forceinline__ void ldsm4(u32* r, u32 addr) {
    asm volatile("ldmatrix.sync.aligned.m8n8.x4.shared.b16 {%0,%1,%2,%3},[%4];"
                 : "=r"(r[0]), "=r"(r[1]), "=r"(r[2]), "=r"(r[3]) : "r"(addr));
}

// ---------------- K0: nerf encoding ------------------------------------------
__global__ __launch_bounds__(256) void enc_kernel(const float* __restrict__ x) {
    int p = blockIdx.x * 256 + threadIdx.x;
    float x0 = x[2 * p], x1 = x[2 * p + 1];
    float* o = g_enc + p * 64;
    const float HPI = 1.5707963267948966f;
    o[0] = x0; o[1] = x1;
#pragma unroll
    for (int s = 0; s < 15; ++s) {
        float sc = (float)(1 << s);
        float a0 = x0 * sc, a1 = x1 * sc;
        o[2 + 2 * s]  = sin_cw(a0);
        o[3 + 2 * s]  = sin_cw(a1);
        o[32 + 2 * s] = sin_cw(a0 + HPI);
        o[33 + 2 * s] = sin_cw(a1 + HPI);
    }
    o[62] = 0.0f; o[63] = 0.0f;
}

// ---------------- K1: hyper weight generation --------------------------------
struct HP {
    const float* pw[4];
    const float* pb[4];
    const float* lnw[4];
    const float* lnb[4];
};

__global__ __launch_bounds__(256) void hyperw_kernel(const float* __restrict__ sdf, HP hp) {
    __shared__ float wbuf[30 * 62];
    int b  = blockIdx.x & 15;
    int li = blockIdx.x >> 4;
    int c    = (li == 0) ? 62 : 30;
    int woff = (li == 0) ? 0  : 1860 + (li - 1) * 900;
    const float* pw  = hp.pw[li];
    const float* pb  = hp.pb[li];
    const float* lnw = hp.lnw[li];
    const float* lnb = hp.lnb[li];

    int tid = threadIdx.x;
    int tot = 30 * c;
    for (int e = tid; e < tot; e += 256) {
        int v = e / c, cc = e - v * c;
        const float4* sl4 = (const float4*)(sdf + ((b * 120) + li * 30 + v) * 120);
        const float4* pw4 = (const float4*)(pw + (v * c + cc) * 120);
        float acc = 0.0f;
#pragma unroll
        for (int d = 0; d < 30; ++d) {
            float4 a = sl4[d], w = pw4[d];
            acc = fmaf(a.x, w.x, acc); acc = fmaf(a.y, w.y, acc);
            acc = fmaf(a.z, w.z, acc); acc = fmaf(a.w, w.w, acc);
        }
        wbuf[e] = acc + pb[e];
    }
    __syncthreads();
    if (tid < 30) {
        int v = tid;
        const float* row = wbuf + v * c;
        float mu = 0.0f;
        for (int cc = 0; cc < c; ++cc) mu += row[cc];
        mu /= (float)c;
        float var = 0.0f;
        for (int cc = 0; cc < c; ++cc) { float d = row[cc] - mu; var = fmaf(d, d, var); }
        var /= (float)c;
        float inv = rsqrtf(var + 1e-5f);
        float* dst = g_W + b * WSTRIDE + woff + v * c;
        for (int cc = 0; cc < c; ++cc)
            dst[cc] = (row[cc] - mu) * inv * lnw[cc] + lnb[cc];
    }
}

// ---------------- K2: apply 4 hyper layers -----------------------------------
__global__ __launch_bounds__(256) void hyper_apply_kernel(
    const float* __restrict__ b0, const float* __restrict__ b1,
    const float* __restrict__ b2, const float* __restrict__ b3) {
    __shared__ float sW[WSTRIDE];
    __shared__ float sb[120];
    int b = blockIdx.y;
    int tid = threadIdx.x;
    const float* Wb = g_W + b * WSTRIDE;
    for (int i = tid; i < WSTRIDE; i += 256) sW[i] = Wb[i];
    if (tid < 30) sb[tid] = b0[tid];
    else if (tid < 60) sb[tid] = b1[tid - 30];
    else if (tid < 90) sb[tid] = b2[tid - 60];
    else if (tid < 120) sb[tid] = b3[tid - 90];
    __syncthreads();

    int p = blockIdx.x * 256 + tid;
    u64 hpr[31];
    const u64* e8 = (const u64*)(g_enc + p * 64);
#pragma unroll
    for (int i = 0; i < 31; ++i) hpr[i] = e8[i];

    float a[30];
#pragma unroll
    for (int oo = 0; oo < 30; ++oo) {
        const u64* w8 = (const u64*)(sW + oo * 62);
        u64 acc = 0ull;
#pragma unroll
        for (int i = 0; i < 31; ++i) acc = fma2(hpr[i], w8[i], acc);
        float2 f = up2(acc);
        a[oo] = silu_f(f.x + f.y + sb[oo]);
    }
#pragma unroll
    for (int l = 1; l <= 3; ++l) {
        int off = 1860 + (l - 1) * 900;
        u64 ap[15];
#pragma unroll
        for (int i = 0; i < 15; ++i) ap[i] = pk2(a[2 * i], a[2 * i + 1]);
        float t[30];
#pragma unroll
        for (int oo = 0; oo < 30; ++oo) {
            const u64* w8 = (const u64*)(sW + off + oo * 30);
            u64 acc = 0ull;
#pragma unroll
            for (int i = 0; i < 15; ++i) acc = fma2(ap[i], w8[i], acc);
            float2 f = up2(acc);
            t[oo] = silu_f(f.x + f.y + sb[l * 30 + oo]);
        }
#pragma unroll
        for (int oo = 0; oo < 30; ++oo) a[oo] = t[oo];
    }
    u64* gout = (u64*)(g_g + ((size_t)b * NPTS + p) * 30);
#pragma unroll
    for (int i = 0; i < 15; ++i) gout[i] = pk2(a[2 * i], a[2 * i + 1]);
}

// ---------------- K3: persistent MLP, 512 thr, mma.sync bf16x3 ---------------
// A = W1 [128 j][256 k] bf16 hi/lo, pitch 132 words (528 B).
// B = S  [64 p][256 k]  bf16 hi/lo, pitch 132 words + (p>>5)*4-word shift.
// 16 warps = (mg 8, ng 2); warp tile 16j x 32p; ldmatrix.x4 fragments.
// Accumulators: c = AhBh, d = AhBl + AlBh (independent chains), merged in epi.
#define AP 132
#define SM_A_HI 0
#define SM_A_LO 67584
#define SM_B_HI 135168
#define SM_B_LO 168992
#define SM_GP   202816   // 15 rows x 72 u64 = 8640 B
#define SM_SB1  211456
#define SM_SW2  211968
#define SM_RED  212480   // 16 x 36 floats
#define K3_SMEM_BYTES 214784
#define GP_STRIDE 72
#define TILE_P 64
#define MLP_BLOCKS 148
#define MLP_THREADS 512
#define N_ITEMS ((NPTS / TILE_P) * NB)

__global__ __launch_bounds__(MLP_THREADS, 1) void mlp_kernel(
    const float* __restrict__ w0, const float* __restrict__ b0,
    const float* __restrict__ w1, const float* __restrict__ b1,
    const float* __restrict__ w2, const float* __restrict__ b2v,
    float* __restrict__ out) {
    extern __shared__ char smem[];
    float* smf = (float*)smem;
    u32 sbase = smem_u32(smem);
    int tid = threadIdx.x, wid = tid >> 5, lane = tid & 31;

    // ---- stage W1 hi/lo (once) ----
    for (int idx = tid; idx < 128 * 256; idx += MLP_THREADS) {
        int j = idx >> 8, k = idx & 255;
        float w = w1[idx];
        __nv_bfloat16 h = __float2bfloat16(w);
        __nv_bfloat16 l = __float2bfloat16(w - __bfloat162float(h));
        int byte = (j * AP + (k >> 1)) * 4 + (k & 1) * 2;
        *(__nv_bfloat16*)(smem + SM_A_HI + byte) = h;
        *(__nv_bfloat16*)(smem + SM_A_LO + byte) = l;
    }
    if (tid < 128) { smf[SM_SB1 / 4 + tid] = b1[tid]; smf[SM_SW2 / 4 + tid] = w2[tid]; }
    float bias2 = __ldg(b2v);

    // phase1 coords: thread = (kp 128, phq 4) -> rows 2kp,2kp+1 x 16 points
    int kp = tid >> 2, phq = tid & 3;
    float b00 = b0[2 * kp], b01 = b0[2 * kp + 1];
    const u64* w0g = (const u64*)(w0 + kp * 60);
    u64* sGp = (u64*)(smem + SM_GP);

    // mma coords
    int mg = wid >> 1, ng = wid & 1, r = lane >> 2, q = lane & 3;

    u32 aAdrH, aAdrL, bAdrH[2], bAdrL[2];
    {
        int arow = mg * 16 + ((lane >> 3) & 1) * 8 + (lane & 7);
        int achk = ((lane >> 4) & 1) * 16;
        aAdrH = sbase + SM_A_HI + arow * 528 + achk;
        aAdrL = sbase + SM_A_LO + arow * 528 + achk;
        int bchk = ((lane >> 3) & 1) * 16;
#pragma unroll
        for (int P = 0; P < 2; ++P) {
            int brow = ng * 32 + P * 16 + ((lane >> 4) & 1) * 8 + (lane & 7);
            int bbyte = brow * 528 + ((brow >> 5) & 1) * 16 + bchk;
            bAdrH[P] = sbase + SM_B_HI + bbyte;
            bAdrL[P] = sbase + SM_B_LO + bbyte;
        }
    }

#pragma unroll 1
    for (int item = blockIdx.x; item < N_ITEMS; item += MLP_BLOCKS) {
        int p0 = (item >> 4) * TILE_P;
        int b = item & 15;

        // ---- load g tile: slot = p + 2*(p>>4), pitch 72 u64 ----
        for (int idx = tid; idx < 960; idx += MLP_THREADS) {
            int p = idx / 15, i = idx - p * 15;
            sGp[i * GP_STRIDE + p + 2 * (p >> 4)] =
                *(const u64*)(g_g + ((size_t)b * NPTS + p0 + p) * 30 + 2 * i);
        }
        __syncthreads();

        // ---- phase 1: rows 2kp,2kp+1 x 16 pts; emit bf16 hi/lo S ----
        {
            u64 w0r0[15], w0r1[15];
#pragma unroll
            for (int i = 0; i < 15; ++i) {
                asm volatile("ld.global.nc.b64 %0,[%1];" : "=l"(w0r0[i]) : "l"(w0g + i));
                asm volatile("ld.global.nc.b64 %0,[%1];" : "=l"(w0r1[i]) : "l"(w0g + 15 + i));
            }
#pragma unroll 1
            for (int pb = 0; pb < 4; ++pb) {
                const u64* gb = sGp + phq * 18 + pb * 4;
                u64 a0[4], a1[4];
#pragma unroll
                for (int u = 0; u < 4; ++u) { a0[u] = 0ull; a1[u] = 0ull; }
#pragma unroll
                for (int i = 0; i < 15; ++i) {
                    ulonglong2 gA = *(const ulonglong2*)(gb + i * GP_STRIDE);
                    ulonglong2 gB = *(const ulonglong2*)(gb + i * GP_STRIDE + 2);
                    a0[0] = fma2(w0r0[i], gA.x, a0[0]); a1[0] = fma2(w0r1[i], gA.x, a1[0]);
                    a0[1] = fma2(w0r0[i], gA.y, a0[1]); a1[1] = fma2(w0r1[i], gA.y, a1[1]);
                    a0[2] = fma2(w0r0[i], gB.x, a0[2]); a1[2] = fma2(w0r1[i], gB.x, a1[2]);
                    a0[3] = fma2(w0r0[i], gB.y, a0[3]); a1[3] = fma2(w0r1[i], gB.y, a1[3]);
                }
#pragma unroll
                for (int u = 0; u < 4; ++u) {
                    int p = phq * 16 + pb * 4 + u;
                    float2 f0 = up2(a0[u]), f1 = up2(a1[u]);
                    float s0 = silu_f(f0.x + f0.y + b00);
                    float s1 = silu_f(f1.x + f1.y + b01);
                    __nv_bfloat16 h0 = __float2bfloat16(s0);
                    __nv_bfloat16 h1 = __float2bfloat16(s1);
                    float l0f = s0 - __bfloat162float(h0);
                    float l1f = s1 - __bfloat162float(h1);
                    int word = p * AP + (p >> 5) * 4 + kp;
                    __nv_bfloat162 hh; hh.x = h0; hh.y = h1;
                    ((u32*)(smem + SM_B_HI))[word] = *(u32*)&hh;
                    ((u32*)(smem + SM_B_LO))[word] = pack_bf2(l0f, l1f);
                }
            }
        }
        __syncthreads();

        // ---- mma: warp tile 16j x 32p, K=256, pass-major, split acc ----
        float c[4][4], d[4][4];
#pragma unroll
        for (int nt = 0; nt < 4; ++nt)
#pragma unroll
            for (int e = 0; e < 4; ++e) { c[nt][e] = 0.0f; d[nt][e] = 0.0f; }

#pragma unroll 4
        for (int kt = 0; kt < 16; ++kt) {
            int kb = kt * 32;
            u32 ah[4], al[4], bh[2][4], bl[2][4];
            ldsm4(ah, aAdrH + kb);
            ldsm4(al, aAdrL + kb);
            ldsm4(bh[0], bAdrH[0] + kb);
            ldsm4(bh[1], bAdrH[1] + kb);
            ldsm4(bl[0], bAdrL[0] + kb);
            ldsm4(bl[1], bAdrL[1] + kb);
            // pass hh -> c
#pragma unroll
            for (int P = 0; P < 2; ++P)
#pragma unroll
                for (int s = 0; s < 2; ++s)
                    mma16816(c[2 * P + s], ah, bh[P] + 2 * s);
            // pass hl -> d
#pragma unroll
            for (int P = 0; P < 2; ++P)
#pragma unroll
                for (int s = 0; s < 2; ++s)
                    mma16816(d[2 * P + s], ah, bl[P] + 2 * s);
            // pass lh -> d
#pragma unroll
            for (int P = 0; P < 2; ++P)
#pragma unroll
                for (int s = 0; s < 2; ++s)
                    mma16816(d[2 * P + s], al, bh[P] + 2 * s);
        }

        // ---- epilogue: silu + w2 per element, reduce over j ----
        float pacc[8];
#pragma unroll
        for (int e = 0; e < 8; ++e) pacc[e] = 0.0f;
        {
            int jA = mg * 16 + r;
            float b1A = smf[SM_SB1 / 4 + jA],     w2A = smf[SM_SW2 / 4 + jA];
            float b1B = smf[SM_SB1 / 4 + jA + 8], w2B = smf[SM_SW2 / 4 + jA + 8];
#pragma unroll
            for (int nt = 0; nt < 4; ++nt) {
                float* cc = c[nt];
                float* dd = d[nt];
                pacc[nt * 2 + 0] += w2A * silu_f(cc[0] + dd[0] + b1A)
                                  + w2B * silu_f(cc[2] + dd[2] + b1B);
                pacc[nt * 2 + 1] += w2A * silu_f(cc[1] + dd[1] + b1A)
                                  + w2B * silu_f(cc[3] + dd[3] + b1B);
            }
        }
#pragma unroll
        for (int e = 0; e < 8; ++e) {
            pacc[e] += __shfl_xor_sync(0xffffffffu, pacc[e], 16);
            pacc[e] += __shfl_xor_sync(0xffffffffu, pacc[e], 8);
            pacc[e] += __shfl_xor_sync(0xffffffffu, pacc[e], 4);
        }
        if (lane < 4) {
#pragma unroll
            for (int e = 0; e < 8; ++e) {
                int lp = (e >> 1) * 8 + lane * 2 + (e & 1);
                smf[SM_RED / 4 + wid * 36 + lp] = pacc[e];
            }
        }
        __syncthreads();
        if (tid < 64) {
            int p = tid, ngx = p >> 5, lp = p & 31;
            float s = bias2;
#pragma unroll
            for (int m = 0; m < 8; ++m)
                s += smf[SM_RED / 4 + (m * 2 + ngx) * 36 + lp];
            out[(size_t)b * NPTS + p0 + p] = s;
        }
        __syncthreads();
    }
}

// ---------------- launch -----------------------------------------------------
extern "C" void kernel_launch(void* const* d_in, const int* in_sizes, int n_in,
                              void* d_out, int out_size) {
    const float* x   = (const float*)d_in[0];
    const float* sdf = (const float*)d_in[1];
    HP hp;
    hp.pw[0]  = (const float*)d_in[2];  hp.pw[1]  = (const float*)d_in[7];
    hp.pw[2]  = (const float*)d_in[12]; hp.pw[3]  = (const float*)d_in[17];
    hp.pb[0]  = (const float*)d_in[3];  hp.pb[1]  = (const float*)d_in[8];
    hp.pb[2]  = (const float*)d_in[13]; hp.pb[3]  = (const float*)d_in[18];
    hp.lnw[0] = (const float*)d_in[4];  hp.lnw[1] = (const float*)d_in[9];
    hp.lnw[2] = (const float*)d_in[14]; hp.lnw[3] = (const float*)d_in[19];
    hp.lnb[0] = (const float*)d_in[5];  hp.lnb[1] = (const float*)d_in[10];
    hp.lnb[2] = (const float*)d_in[15]; hp.lnb[3] = (const float*)d_in[20];
    const float* bias[4] = {(const float*)d_in[6],  (const float*)d_in[11],
                            (const float*)d_in[16], (const float*)d_in[21]};
    const float* mw0 = (const float*)d_in[22];
    const float* mb0 = (const float*)d_in[23];
    const float* mw1 = (const float*)d_in[24];
    const float* mb1 = (const float*)d_in[25];
    const float* mw2 = (const float*)d_in[26];
    const float* mb2 = (const float*)d_in[27];
    float* out = (float*)d_out;

    cudaFuncSetAttribute(mlp_kernel, cudaFuncAttributeMaxDynamicSharedMemorySize,
                         K3_SMEM_BYTES);

    enc_kernel<<<NPTS / 256, 256>>>(x);
    hyperw_kernel<<<NB * 4, 256>>>(sdf, hp);

    dim3 g2(NPTS / 256, NB);
    hyper_apply_kernel<<<g2, 256>>>(bias[0], bias[1], bias[2], bias[3]);

    mlp_kernel<<<MLP_BLOCKS, MLP_THREADS, K3_SMEM_BYTES>>>(mw0, mb0, mw1, mb1,
                                                           mw2, mb2, out);
}

// round 15
// speedup vs baseline: 1.3454x; 1.3454x over previous
#include <cuda_runtime.h>
#include <cuda_bf16.h>
#include <cuda_fp16.h>
#include <math.h>

#define NPTS 32768
#define NB 16
#define WSTRIDE 4560

typedef unsigned long long u64;
typedef unsigned int u32;

// ---------------- scratch ----------------------------------------------------
__device__ float g_W[NB * WSTRIDE];
__device__ float g_enc[NPTS * 64];
__device__ float g_g[NB * NPTS * 30];

// ---------------- packed f32x2 helpers ---------------------------------------
__device__ __forceinline__ u64 pk2(float lo, float hi) {
    u64 r; asm("mov.b64 %0,{%1,%2};" : "=l"(r) : "f"(lo), "f"(hi)); return r;
}
__device__ __forceinline__ float2 up2(u64 v) {
    float2 r; asm("mov.b64 {%0,%1},%2;" : "=f"(r.x), "=f"(r.y) : "l"(v)); return r;
}
__device__ __forceinline__ u64 fma2(u64 a, u64 b, u64 c) {
    u64 r; asm("fma.rn.f32x2 %0,%1,%2,%3;" : "=l"(r) : "l"(a), "l"(b), "l"(c));
    return r;
}

// ---------------- misc -------------------------------------------------------
__device__ __forceinline__ float silu_f(float z) {
    float e = __expf(-z);
    return __fdividef(z, 1.0f + e);
}
__device__ __forceinline__ float sin_cw(float x) {
    float kf = rintf(x * 0.63661977236758138f);
    float r = fmaf(kf, -1.57079637e+00f, x);
    r = fmaf(kf, 4.37113883e-08f, r);
    r = fmaf(kf, 1.71512489e-15f, r);
    int q = (int)kf;
    float s2 = r * r;
    float ps = fmaf(s2, 2.7525562e-6f, -1.9840874e-4f);
    ps = fmaf(s2, ps, 8.3333310e-3f);
    ps = fmaf(s2, ps, -1.6666667e-1f);
    float sinv = fmaf(r * s2, ps, r);
    float pc = fmaf(s2, 2.4433157e-5f, -1.3888378e-3f);
    pc = fmaf(s2, pc, 4.1666638e-2f);
    pc = fmaf(s2, pc, -0.5f);
    float cosv = fmaf(s2, pc, 1.0f);
    float res = (q & 1) ? cosv : sinv;
    if (q & 2) res = -res;
    return res;
}
__device__ __forceinline__ u32 smem_u32(const void* p) {
    u32 a;
    asm("{ .reg .u64 t; cvta.to.shared.u64 t, %1; cvt.u32.u64 %0, t; }"
        : "=r"(a) : "l"(p));
    return a;
}

// mma.sync m16n8k16 fp16 (baseline PTX, works on plain sm_100)
__device__ __forceinline__ void mma16816h(float c[4], const u32 a[4], const u32* b) {
    asm volatile(
        "mma.sync.aligned.m16n8k16.row.col.f32.f16.f16.f32 "
        "{%0,%1,%2,%3},{%4,%5,%6,%7},{%8,%9},{%0,%1,%2,%3};"
        : "+f"(c[0]), "+f"(c[1]), "+f"(c[2]), "+f"(c[3])
        : "r"(a[0]), "r"(a[1]), "r"(a[2]), "r"(a[3]), "r"(b[0]), "r"(b[1]));
}
// ldmatrix x4 (baseline PTX, sm_75+)
__device__ __forceinline__ void ldsm4(u32* r, u32 addr) {
    asm volatile("ldmatrix.sync.aligned.m8n8.x4.shared.b16 {%0,%1,%2,%3},[%4];"
                 : "=r"(r[0]), "=r"(r[1]), "=r"(r[2]), "=r"(r[3]) : "r"(addr));
}

// ---------------- K0: nerf encoding ------------------------------------------
__global__ __launch_bounds__(256) void enc_kernel(const float* __restrict__ x) {
    int p = blockIdx.x * 256 + threadIdx.x;
    float x0 = x[2 * p], x1 = x[2 * p + 1];
    float* o = g_enc + p * 64;
    const float HPI = 1.5707963267948966f;
    o[0] = x0; o[1] = x1;
#pragma unroll
    for (int s = 0; s < 15; ++s) {
        float sc = (float)(1 << s);
        float a0 = x0 * sc, a1 = x1 * sc;
        o[2 + 2 * s]  = sin_cw(a0);
        o[3 + 2 * s]  = sin_cw(a1);
        o[32 + 2 * s] = sin_cw(a0 + HPI);
        o[33 + 2 * s] = sin_cw(a1 + HPI);
    }
    o[62] = 0.0f; o[63] = 0.0f;
}

// ---------------- K1: hyper weight generation --------------------------------
struct HP {
    const float* pw[4];
    const float* pb[4];
    const float* lnw[4];
    const float* lnb[4];
};

__global__ __launch_bounds__(256) void hyperw_kernel(const float* __restrict__ sdf, HP hp) {
    __shared__ float wbuf[30 * 62];
    int b  = blockIdx.x & 15;
    int li = blockIdx.x >> 4;
    int c    = (li == 0) ? 62 : 30;
    int woff = (li == 0) ? 0  : 1860 + (li - 1) * 900;
    const float* pw  = hp.pw[li];
    const float* pb  = hp.pb[li];
    const float* lnw = hp.lnw[li];
    const float* lnb = hp.lnb[li];

    int tid = threadIdx.x;
    int tot = 30 * c;
    for (int e = tid; e < tot; e += 256) {
        int v = e / c, cc = e - v * c;
        const float4* sl4 = (const float4*)(sdf + ((b * 120) + li * 30 + v) * 120);
        const float4* pw4 = (const float4*)(pw + (v * c + cc) * 120);
        float acc = 0.0f;
#pragma unroll
        for (int d = 0; d < 30; ++d) {
            float4 a = sl4[d], w = pw4[d];
            acc = fmaf(a.x, w.x, acc); acc = fmaf(a.y, w.y, acc);
            acc = fmaf(a.z, w.z, acc); acc = fmaf(a.w, w.w, acc);
        }
        wbuf[e] = acc + pb[e];
    }
    __syncthreads();
    if (tid < 30) {
        int v = tid;
        const float* row = wbuf + v * c;
        float mu = 0.0f;
        for (int cc = 0; cc < c; ++cc) mu += row[cc];
        mu /= (float)c;
        float var = 0.0f;
        for (int cc = 0; cc < c; ++cc) { float d = row[cc] - mu; var = fmaf(d, d, var); }
        var /= (float)c;
        float inv = rsqrtf(var + 1e-5f);
        float* dst = g_W + b * WSTRIDE + woff + v * c;
        for (int cc = 0; cc < c; ++cc)
            dst[cc] = (row[cc] - mu) * inv * lnw[cc] + lnb[cc];
    }
}

// ---------------- K2: apply 4 hyper layers -----------------------------------
__global__ __launch_bounds__(256) void hyper_apply_kernel(
    const float* __restrict__ b0, const float* __restrict__ b1,
    const float* __restrict__ b2, const float* __restrict__ b3) {
    __shared__ float sW[WSTRIDE];
    __shared__ float sb[120];
    int b = blockIdx.y;
    int tid = threadIdx.x;
    const float* Wb = g_W + b * WSTRIDE;
    for (int i = tid; i < WSTRIDE; i += 256) sW[i] = Wb[i];
    if (tid < 30) sb[tid] = b0[tid];
    else if (tid < 60) sb[tid] = b1[tid - 30];
    else if (tid < 90) sb[tid] = b2[tid - 60];
    else if (tid < 120) sb[tid] = b3[tid - 90];
    __syncthreads();

    int p = blockIdx.x * 256 + tid;
    u64 hpr[31];
    const u64* e8 = (const u64*)(g_enc + p * 64);
#pragma unroll
    for (int i = 0; i < 31; ++i) hpr[i] = e8[i];

    float a[30];
#pragma unroll
    for (int oo = 0; oo < 30; ++oo) {
        const u64* w8 = (const u64*)(sW + oo * 62);
        u64 acc = 0ull;
#pragma unroll
        for (int i = 0; i < 31; ++i) acc = fma2(hpr[i], w8[i], acc);
        float2 f = up2(acc);
        a[oo] = silu_f(f.x + f.y + sb[oo]);
    }
#pragma unroll
    for (int l = 1; l <= 3; ++l) {
        int off = 1860 + (l - 1) * 900;
        u64 ap[15];
#pragma unroll
        for (int i = 0; i < 15; ++i) ap[i] = pk2(a[2 * i], a[2 * i + 1]);
        float t[30];
#pragma unroll
        for (int oo = 0; oo < 30; ++oo) {
            const u64* w8 = (const u64*)(sW + off + oo * 30);
            u64 acc = 0ull;
#pragma unroll
            for (int i = 0; i < 15; ++i) acc = fma2(ap[i], w8[i], acc);
            float2 f = up2(acc);
            t[oo] = silu_f(f.x + f.y + sb[l * 30 + oo]);
        }
#pragma unroll
        for (int oo = 0; oo < 30; ++oo) a[oo] = t[oo];
    }
    u64* gout = (u64*)(g_g + ((size_t)b * NPTS + p) * 30);
#pragma unroll
    for (int i = 0; i < 15; ++i) gout[i] = pk2(a[2 * i], a[2 * i + 1]);
}

// ---------------- K3: persistent MLP, layer-2 on mma.sync fp16 (1 pass) ------
// A = W1 [128 j][256 k] fp16, pitch 132 words (528 B).
// B = S  [64 p][256 k]  fp16, pitch 132 words + (p>>5)*4-word shift.
// 8 warps = (mg 4, ng 2); warp tile 32j x 32p; ldmatrix.x4 fragments.
// 112 KB smem -> 2 blocks/SM (grid 296): cross-block phase overlap.
#define AP 132
#define SM_A    0        // 128*528 = 67584
#define SM_B    67584    // 64*528 = 33792 -> 101376
#define SM_GP   101376   // 15 rows x 68 u64 = 8160 -> 109536
#define SM_SB1  109536   // 512 -> 110048
#define SM_SW2  110048   // 512 -> 110560
#define SM_RED  110560   // 8 x 36 floats = 1152 -> 111712
#define K3_SMEM_BYTES 111712
#define TILE_P 64
#define MLP_BLOCKS 296
#define N_ITEMS ((NPTS / TILE_P) * NB)

__global__ __launch_bounds__(256, 2) void mlp_kernel(
    const float* __restrict__ w0, const float* __restrict__ b0,
    const float* __restrict__ w1, const float* __restrict__ b1,
    const float* __restrict__ w2, const float* __restrict__ b2v,
    float* __restrict__ out) {
    extern __shared__ char smem[];
    float* smf = (float*)smem;
    u32 sbase = smem_u32(smem);
    int tid = threadIdx.x, wid = tid >> 5, lane = tid & 31;

    // ---- stage W1 fp16 (once) ----
    for (int idx = tid; idx < 128 * 256; idx += 256) {
        int j = idx >> 8, k = idx & 255;
        int byte = (j * AP + (k >> 1)) * 4 + (k & 1) * 2;
        *(__half*)(smem + SM_A + byte) = __float2half_rn(w1[idx]);
    }
    if (tid < 128) { smf[SM_SB1 / 4 + tid] = b1[tid]; smf[SM_SW2 / 4 + tid] = w2[tid]; }
    float bias2 = __ldg(b2v);

    // phase1 coords: thread = (kp 128, ph 2) -> rows 2kp,2kp+1 x 32 points
    int kp = tid >> 1, ph = tid & 1;
    float b00 = b0[2 * kp], b01 = b0[2 * kp + 1];
    const u64* w0g = (const u64*)(w0 + kp * 60);
    u64* sGp = (u64*)(smem + SM_GP);

    // mma coords
    int mg = wid >> 1, ng = wid & 1, r = lane >> 2;

    u32 aAdr[2], bAdr[2];
    {
        int arow = mg * 32 + ((lane >> 3) & 1) * 8 + (lane & 7);
        int achk = ((lane >> 4) & 1) * 16;
        aAdr[0] = sbase + SM_A + arow * 528 + achk;
        aAdr[1] = aAdr[0] + 16 * 528;
        int bchk = ((lane >> 3) & 1) * 16;
#pragma unroll
        for (int P = 0; P < 2; ++P) {
            int brow = ng * 32 + P * 16 + ((lane >> 4) & 1) * 8 + (lane & 7);
            int bbyte = brow * 528 + ((brow >> 5) & 1) * 16 + bchk;
            bAdr[P] = sbase + SM_B + bbyte;
        }
    }

#pragma unroll 1
    for (int item = blockIdx.x; item < N_ITEMS; item += MLP_BLOCKS) {
        int p0 = (item >> 4) * TILE_P;
        int b = item & 15;

        // ---- load g tile: [i][slot], slot = p + 2*(p>>5), pitch 68 u64 ----
        for (int idx = tid; idx < 960; idx += 256) {
            int p = idx / 15, i = idx - p * 15;
            sGp[i * 68 + p + 2 * (p >> 5)] =
                *(const u64*)(g_g + ((size_t)b * NPTS + p0 + p) * 30 + 2 * i);
        }
        __syncthreads();

        // ---- phase 1: rows 2kp,2kp+1 x 32 pts; emit fp16 S ----
        {
            u64 w0r0[15], w0r1[15];
#pragma unroll
            for (int i = 0; i < 15; ++i) {
                asm volatile("ld.global.nc.b64 %0,[%1];" : "=l"(w0r0[i]) : "l"(w0g + i));
                asm volatile("ld.global.nc.b64 %0,[%1];" : "=l"(w0r1[i]) : "l"(w0g + 15 + i));
            }
#pragma unroll 1
            for (int pb = 0; pb < 8; ++pb) {
                const u64* gb = sGp + ph * 34 + pb * 4;
                u64 a0[4], a1[4];
#pragma unroll
                for (int u = 0; u < 4; ++u) { a0[u] = 0ull; a1[u] = 0ull; }
#pragma unroll
                for (int i = 0; i < 15; ++i) {
                    ulonglong2 gA = *(const ulonglong2*)(gb + i * 68);
                    ulonglong2 gB = *(const ulonglong2*)(gb + i * 68 + 2);
                    a0[0] = fma2(w0r0[i], gA.x, a0[0]); a1[0] = fma2(w0r1[i], gA.x, a1[0]);
                    a0[1] = fma2(w0r0[i], gA.y, a0[1]); a1[1] = fma2(w0r1[i], gA.y, a1[1]);
                    a0[2] = fma2(w0r0[i], gB.x, a0[2]); a1[2] = fma2(w0r1[i], gB.x, a1[2]);
                    a0[3] = fma2(w0r0[i], gB.y, a0[3]); a1[3] = fma2(w0r1[i], gB.y, a1[3]);
                }
#pragma unroll
                for (int u = 0; u < 4; ++u) {
                    int p = ph * 32 + pb * 4 + u;
                    float2 f0 = up2(a0[u]), f1 = up2(a1[u]);
                    float s0 = silu_f(f0.x + f0.y + b00);
                    float s1 = silu_f(f1.x + f1.y + b01);
                    int word = p * AP + (p >> 5) * 4 + kp;
                    __half2 hh = __floats2half2_rn(s0, s1);
                    ((u32*)(smem + SM_B))[word] = *(u32*)&hh;
                }
            }
        }
        __syncthreads();

        // ---- mma: warp tile 32j x 32p, K=256, single fp16 pass ----
        float c[2][4][4];
#pragma unroll
        for (int mt = 0; mt < 2; ++mt)
#pragma unroll
            for (int nt = 0; nt < 4; ++nt)
#pragma unroll
                for (int e = 0; e < 4; ++e) c[mt][nt][e] = 0.0f;

#pragma unroll 4
        for (int kt = 0; kt < 16; ++kt) {
            int kb = kt * 32;
            u32 ah[2][4], bh[2][4];
            ldsm4(ah[0], aAdr[0] + kb);
            ldsm4(ah[1], aAdr[1] + kb);
            ldsm4(bh[0], bAdr[0] + kb);
            ldsm4(bh[1], bAdr[1] + kb);
#pragma unroll
            for (int mt = 0; mt < 2; ++mt)
#pragma unroll
                for (int P = 0; P < 2; ++P)
#pragma unroll
                    for (int s = 0; s < 2; ++s)
                        mma16816h(c[mt][2 * P + s], ah[mt], bh[P] + 2 * s);
        }

        // ---- epilogue: silu + w2 per element, reduce over j ----
        float pacc[8];
#pragma unroll
        for (int e = 0; e < 8; ++e) pacc[e] = 0.0f;
#pragma unroll
        for (int mt = 0; mt < 2; ++mt) {
            int jA = mg * 32 + mt * 16 + r;
            float b1A = smf[SM_SB1 / 4 + jA],     w2A = smf[SM_SW2 / 4 + jA];
            float b1B = smf[SM_SB1 / 4 + jA + 8], w2B = smf[SM_SW2 / 4 + jA + 8];
#pragma unroll
            for (int nt = 0; nt < 4; ++nt) {
                float* cc = c[mt][nt];
                pacc[nt * 2 + 0] += w2A * silu_f(cc[0] + b1A) + w2B * silu_f(cc[2] + b1B);
                pacc[nt * 2 + 1] += w2A * silu_f(cc[1] + b1A) + w2B * silu_f(cc[3] + b1B);
            }
        }
#pragma unroll
        for (int e = 0; e < 8; ++e) {
            pacc[e] += __shfl_xor_sync(0xffffffffu, pacc[e], 16);
            pacc[e] += __shfl_xor_sync(0xffffffffu, pacc[e], 8);
            pacc[e] += __shfl_xor_sync(0xffffffffu, pacc[e], 4);
        }
        if (lane < 4) {
#pragma unroll
            for (int e = 0; e < 8; ++e) {
                int lp = (e >> 1) * 8 + lane * 2 + (e & 1);
                smf[SM_RED / 4 + wid * 36 + lp] = pacc[e];
            }
        }
        __syncthreads();
        if (tid < 64) {
            int p = tid, ngx = p >> 5, lp = p & 31;
            float s = bias2;
#pragma unroll
            for (int m = 0; m < 4; ++m)
                s += smf[SM_RED / 4 + (m * 2 + ngx) * 36 + lp];
            out[(size_t)b * NPTS + p0 + p] = s;
        }
        __syncthreads();
    }
}

// ---------------- launch -----------------------------------------------------
extern "C" void kernel_launch(void* const* d_in, const int* in_sizes, int n_in,
                              void* d_out, int out_size) {
    const float* x   = (const float*)d_in[0];
    const float* sdf = (const float*)d_in[1];
    HP hp;
    hp.pw[0]  = (const float*)d_in[2];  hp.pw[1]  = (const float*)d_in[7];
    hp.pw[2]  = (const float*)d_in[12]; hp.pw[3]  = (const float*)d_in[17];
    hp.pb[0]  = (const float*)d_in[3];  hp.pb[1]  = (const float*)d_in[8];
    hp.pb[2]  = (const float*)d_in[13]; hp.pb[3]  = (const float*)d_in[18];
    hp.lnw[0] = (const float*)d_in[4];  hp.lnw[1] = (const float*)d_in[9];
    hp.lnw[2] = (const float*)d_in[14]; hp.lnw[3] = (const float*)d_in[19];
    hp.lnb[0] = (const float*)d_in[5];  hp.lnb[1] = (const float*)d_in[10];
    hp.lnb[2] = (const float*)d_in[15]; hp.lnb[3] = (const float*)d_in[20];
    const float* bias[4] = {(const float*)d_in[6],  (const float*)d_in[11],
                            (const float*)d_in[16], (const float*)d_in[21]};
    const float* mw0 = (const float*)d_in[22];
    const float* mb0 = (const float*)d_in[23];
    const float* mw1 = (const float*)d_in[24];
    const float* mb1 = (const float*)d_in[25];
    const float* mw2 = (const float*)d_in[26];
    const float* mb2 = (const float*)d_in[27];
    float* out = (float*)d_out;

    cudaFuncSetAttribute(mlp_kernel, cudaFuncAttributeMaxDynamicSharedMemorySize,
                         K3_SMEM_BYTES);

    enc_kernel<<<NPTS / 256, 256>>>(x);
    hyperw_kernel<<<NB * 4, 256>>>(sdf, hp);

    dim3 g2(NPTS / 256, NB);
    hyper_apply_kernel<<<g2, 256>>>(bias[0], bias[1], bias[2], bias[3]);

    mlp_kernel<<<MLP_BLOCKS, 256, K3_SMEM_BYTES>>>(mw0, mb0, mw1, mb1, mw2, mb2, out);
}

// round 17
// speedup vs baseline: 1.6187x; 1.2031x over previous
#include <cuda_runtime.h>
#include <cuda_fp16.h>
#include <math.h>

#define NPTS 32768
#define NB 16
#define WSTRIDE 4560

typedef unsigned long long u64;
typedef unsigned int u32;

// ---------------- scratch ----------------------------------------------------
__device__ float g_W[NB * WSTRIDE];
__device__ float g_enc[NPTS * 64];
__device__ float g_g[NB * NPTS * 30];

// ---------------- packed f32x2 helpers ---------------------------------------
__device__ __forceinline__ u64 pk2(float lo, float hi) {
    u64 r; asm("mov.b64 %0,{%1,%2};" : "=l"(r) : "f"(lo), "f"(hi)); return r;
}
__device__ __forceinline__ float2 up2(u64 v) {
    float2 r; asm("mov.b64 {%0,%1},%2;" : "=f"(r.x), "=f"(r.y) : "l"(v)); return r;
}
__device__ __forceinline__ u64 fma2(u64 a, u64 b, u64 c) {
    u64 r; asm("fma.rn.f32x2 %0,%1,%2,%3;" : "=l"(r) : "l"(a), "l"(b), "l"(c));
    return r;
}

// ---------------- misc -------------------------------------------------------
__device__ __forceinline__ float silu_f(float z) {
    float e = __expf(-z);
    return __fdividef(z, 1.0f + e);
}
__device__ __forceinline__ float sin_cw(float x) {
    float kf = rintf(x * 0.63661977236758138f);
    float r = fmaf(kf, -1.57079637e+00f, x);
    r = fmaf(kf, 4.37113883e-08f, r);
    r = fmaf(kf, 1.71512489e-15f, r);
    int q = (int)kf;
    float s2 = r * r;
    float ps = fmaf(s2, 2.7525562e-6f, -1.9840874e-4f);
    ps = fmaf(s2, ps, 8.3333310e-3f);
    ps = fmaf(s2, ps, -1.6666667e-1f);
    float sinv = fmaf(r * s2, ps, r);
    float pc = fmaf(s2, 2.4433157e-5f, -1.3888378e-3f);
    pc = fmaf(s2, pc, 4.1666638e-2f);
    pc = fmaf(s2, pc, -0.5f);
    float cosv = fmaf(s2, pc, 1.0f);
    float res = (q & 1) ? cosv : sinv;
    if (q & 2) res = -res;
    return res;
}
__device__ __forceinline__ u32 smem_u32(const void* p) {
    u32 a;
    asm("{ .reg .u64 t; cvta.to.shared.u64 t, %1; cvt.u32.u64 %0, t; }"
        : "=r"(a) : "l"(p));
    return a;
}

// mma.sync m16n8k16 fp16 (baseline PTX, works on plain sm_100)
__device__ __forceinline__ void mma16816h(float c[4], const u32 a[4], const u32* b) {
    asm volatile(
        "mma.sync.aligned.m16n8k16.row.col.f32.f16.f16.f32 "
        "{%0,%1,%2,%3},{%4,%5,%6,%7},{%8,%9},{%0,%1,%2,%3};"
        : "+f"(c[0]), "+f"(c[1]), "+f"(c[2]), "+f"(c[3])
        : "r"(a[0]), "r"(a[1]), "r"(a[2]), "r"(a[3]), "r"(b[0]), "r"(b[1]));
}
__device__ __forceinline__ void ldsm4(u32* r, u32 addr) {
    asm volatile("ldmatrix.sync.aligned.m8n8.x4.shared.b16 {%0,%1,%2,%3},[%4];"
                 : "=r"(r[0]), "=r"(r[1]), "=r"(r[2]), "=r"(r[3]) : "r"(addr));
}
__device__ __forceinline__ void ldsm4t(u32* r, u32 addr) {
    asm volatile("ldmatrix.sync.aligned.m8n8.x4.trans.shared.b16 {%0,%1,%2,%3},[%4];"
                 : "=r"(r[0]), "=r"(r[1]), "=r"(r[2]), "=r"(r[3]) : "r"(addr));
}

// ---------------- K0: nerf encoding ------------------------------------------
__global__ __launch_bounds__(256) void enc_kernel(const float* __restrict__ x) {
    int p = blockIdx.x * 256 + threadIdx.x;
    float x0 = x[2 * p], x1 = x[2 * p + 1];
    float* o = g_enc + p * 64;
    const float HPI = 1.5707963267948966f;
    o[0] = x0; o[1] = x1;
#pragma unroll
    for (int s = 0; s < 15; ++s) {
        float sc = (float)(1 << s);
        float a0 = x0 * sc, a1 = x1 * sc;
        o[2 + 2 * s]  = sin_cw(a0);
        o[3 + 2 * s]  = sin_cw(a1);
        o[32 + 2 * s] = sin_cw(a0 + HPI);
        o[33 + 2 * s] = sin_cw(a1 + HPI);
    }
    o[62] = 0.0f; o[63] = 0.0f;
}

// ---------------- K1: hyper weight generation --------------------------------
struct HP {
    const float* pw[4];
    const float* pb[4];
    const float* lnw[4];
    const float* lnb[4];
};

__global__ __launch_bounds__(256) void hyperw_kernel(const float* __restrict__ sdf, HP hp) {
    __shared__ float wbuf[30 * 62];
    int b  = blockIdx.x & 15;
    int li = blockIdx.x >> 4;
    int c    = (li == 0) ? 62 : 30;
    int woff = (li == 0) ? 0  : 1860 + (li - 1) * 900;
    const float* pw  = hp.pw[li];
    const float* pb  = hp.pb[li];
    const float* lnw = hp.lnw[li];
    const float* lnb = hp.lnb[li];

    int tid = threadIdx.x;
    int tot = 30 * c;
    for (int e = tid; e < tot; e += 256) {
        int v = e / c, cc = e - v * c;
        const float4* sl4 = (const float4*)(sdf + ((b * 120) + li * 30 + v) * 120);
        const float4* pw4 = (const float4*)(pw + (v * c + cc) * 120);
        float acc = 0.0f;
#pragma unroll
        for (int d = 0; d < 30; ++d) {
            float4 a = sl4[d], w = pw4[d];
            acc = fmaf(a.x, w.x, acc); acc = fmaf(a.y, w.y, acc);
            acc = fmaf(a.z, w.z, acc); acc = fmaf(a.w, w.w, acc);
        }
        wbuf[e] = acc + pb[e];
    }
    __syncthreads();
    if (tid < 30) {
        int v = tid;
        const float* row = wbuf + v * c;
        float mu = 0.0f;
        for (int cc = 0; cc < c; ++cc) mu += row[cc];
        mu /= (float)c;
        float var = 0.0f;
        for (int cc = 0; cc < c; ++cc) { float d = row[cc] - mu; var = fmaf(d, d, var); }
        var /= (float)c;
        float inv = rsqrtf(var + 1e-5f);
        float* dst = g_W + b * WSTRIDE + woff + v * c;
        for (int cc = 0; cc < c; ++cc)
            dst[cc] = (row[cc] - mu) * inv * lnw[cc] + lnb[cc];
    }
}

// ---------------- K2: apply 4 hyper layers -----------------------------------
__global__ __launch_bounds__(256) void hyper_apply_kernel(
    const float* __restrict__ b0, const float* __restrict__ b1,
    const float* __restrict__ b2, const float* __restrict__ b3) {
    __shared__ float sW[WSTRIDE];
    __shared__ float sb[120];
    int b = blockIdx.y;
    int tid = threadIdx.x;
    const float* Wb = g_W + b * WSTRIDE;
    for (int i = tid; i < WSTRIDE; i += 256) sW[i] = Wb[i];
    if (tid < 30) sb[tid] = b0[tid];
    else if (tid < 60) sb[tid] = b1[tid - 30];
    else if (tid < 90) sb[tid] = b2[tid - 60];
    else if (tid < 120) sb[tid] = b3[tid - 90];
    __syncthreads();

    int p = blockIdx.x * 256 + tid;
    u64 hpr[31];
    const u64* e8 = (const u64*)(g_enc + p * 64);
#pragma unroll
    for (int i = 0; i < 31; ++i) hpr[i] = e8[i];

    float a[30];
#pragma unroll
    for (int oo = 0; oo < 30; ++oo) {
        const u64* w8 = (const u64*)(sW + oo * 62);
        u64 acc = 0ull;
#pragma unroll
        for (int i = 0; i < 31; ++i) acc = fma2(hpr[i], w8[i], acc);
        float2 f = up2(acc);
        a[oo] = silu_f(f.x + f.y + sb[oo]);
    }
#pragma unroll
    for (int l = 1; l <= 3; ++l) {
        int off = 1860 + (l - 1) * 900;
        u64 ap[15];
#pragma unroll
        for (int i = 0; i < 15; ++i) ap[i] = pk2(a[2 * i], a[2 * i + 1]);
        float t[30];
#pragma unroll
        for (int oo = 0; oo < 30; ++oo) {
            const u64* w8 = (const u64*)(sW + off + oo * 30);
            u64 acc = 0ull;
#pragma unroll
            for (int i = 0; i < 15; ++i) acc = fma2(ap[i], w8[i], acc);
            float2 f = up2(acc);
            t[oo] = silu_f(f.x + f.y + sb[l * 30 + oo]);
        }
#pragma unroll
        for (int oo = 0; oo < 30; ++oo) a[oo] = t[oo];
    }
    u64* gout = (u64*)(g_g + ((size_t)b * NPTS + p) * 30);
#pragma unroll
    for (int i = 0; i < 15; ++i) gout[i] = pk2(a[2 * i], a[2 * i + 1]);
}

// ---------------- K3: persistent MLP, both layers on mma.sync fp16 -----------
// Phase1: S[256j x 64p] = silu(W0[256x32k] @ G[64p x 32k] + b0)
//   W0 fp16 [j][80B pitch], G fp16 [p][80B pitch] (16B-aligned rows),
//   S fp16 [k(=j)][144B pitch]. 16 warps x (16j x 64p).
// Phase2: H2[128j x 64p] = W1 @ S; A ldmatrix from [j][528B], B ldmatrix.trans
//   from S [k][144B]. 16 warps = (mg 8, ng 2), tile 16j x 32p.
#define SM_W1   0        // 128*528        -> 67584
#define SM_W0   67584    // 256*80         -> 88064
#define SM_G    88064    // 64*80          -> 93184
#define SM_S    93184    // 256*144        -> 130048
#define SM_B0   130048   // 256 f          -> 131072
#define SM_SB1  131072   // 128 f          -> 131584
#define SM_SW2  131584   // 128 f          -> 132096
#define SM_RED  132096   // 16*36 f        -> 134400
#define K3_SMEM_BYTES 134400
#define TILE_P 64
#define MLP_BLOCKS 148
#define MLP_THREADS 512
#define N_ITEMS ((NPTS / TILE_P) * NB)

__global__ __launch_bounds__(MLP_THREADS, 1) void mlp_kernel(
    const float* __restrict__ w0, const float* __restrict__ b0,
    const float* __restrict__ w1, const float* __restrict__ b1,
    const float* __restrict__ w2, const float* __restrict__ b2v,
    float* __restrict__ out) {
    extern __shared__ char smem[];
    float* smf = (float*)smem;
    u32 sbase = smem_u32(smem);
    int tid = threadIdx.x, wid = tid >> 5, lane = tid & 31;

    // ---- one-time staging ----
    for (int idx = tid; idx < 128 * 256; idx += MLP_THREADS) {
        int j = idx >> 8, k = idx & 255;
        int byte = (j * 132 + (k >> 1)) * 4 + (k & 1) * 2;
        *(__half*)(smem + SM_W1 + byte) = __float2half_rn(w1[idx]);
    }
    for (int idx = tid; idx < 256 * 30; idx += MLP_THREADS) {
        int j = idx / 30, k = idx - j * 30;
        *(__half*)(smem + SM_W0 + j * 80 + k * 2) = __float2half_rn(w0[idx]);
    }
    for (int idx = tid; idx < 256 * 5; idx += MLP_THREADS) {
        int j = idx / 5, w = idx - j * 5;
        *(u32*)(smem + SM_W0 + j * 80 + 60 + w * 4) = 0u;   // k pad words 15..19
    }
    for (int idx = tid; idx < 64 * 5; idx += MLP_THREADS) {
        int p = idx / 5, w = idx - p * 5;
        *(u32*)(smem + SM_G + p * 80 + 60 + w * 4) = 0u;    // G pad words 15..19
    }
    if (tid < 256) smf[SM_B0 / 4 + tid] = b0[tid];
    if (tid < 128) { smf[SM_SB1 / 4 + tid] = b1[tid]; smf[SM_SW2 / 4 + tid] = w2[tid]; }
    float bias2 = __ldg(b2v);

    int r = lane >> 2;

    // phase1 ldmatrix addresses (80B pitch: rows 16B-aligned)
    u32 aAdr1, bAdr1[4];
    {
        int arow = wid * 16 + ((lane >> 3) & 1) * 8 + (lane & 7);
        aAdr1 = sbase + SM_W0 + arow * 80 + ((lane >> 4) & 1) * 16;
#pragma unroll
        for (int P = 0; P < 4; ++P) {
            int brow = P * 16 + ((lane >> 4) & 1) * 8 + (lane & 7);
            bAdr1[P] = sbase + SM_G + brow * 80 + ((lane >> 3) & 1) * 16;
        }
    }
    // phase2 addresses
    int mg = wid >> 1, ng = wid & 1;
    u32 aAdr2, bAdr2[2];
    {
        int arow = mg * 16 + ((lane >> 3) & 1) * 8 + (lane & 7);
        aAdr2 = sbase + SM_W1 + arow * 528 + ((lane >> 4) & 1) * 16;
#pragma unroll
        for (int P = 0; P < 2; ++P) {
            int krow = ((lane >> 3) & 1) * 8 + (lane & 7);
            int pcol = ng * 32 + P * 16 + ((lane >> 4) & 1) * 8;
            bAdr2[P] = sbase + SM_S + krow * 144 + pcol * 2;
        }
    }

#pragma unroll 1
    for (int item = blockIdx.x; item < N_ITEMS; item += MLP_BLOCKS) {
        int p0 = (item >> 4) * TILE_P;
        int b = item & 15;

        // ---- stage G fp16: [p][word i], pitch 80B ----
        for (int idx = tid; idx < 960; idx += MLP_THREADS) {
            int p = idx / 15, i = idx - p * 15;
            u64 v = *(const u64*)(g_g + ((size_t)b * NPTS + p0 + p) * 30 + 2 * i);
            float2 f = up2(v);
            __half2 h = __floats2half2_rn(f.x, f.y);
            *(u32*)(smem + SM_G + p * 80 + i * 4) = *(u32*)&h;
        }
        __syncthreads();

        // ---- phase 1 mma: warp = 16j x 64p, K=32 ----
        {
            float c1[8][4];
#pragma unroll
            for (int nt = 0; nt < 8; ++nt)
#pragma unroll
                for (int e = 0; e < 4; ++e) c1[nt][e] = 0.0f;
#pragma unroll
            for (int kt = 0; kt < 2; ++kt) {
                int kb = kt * 32;
                u32 a[4], bb[4][4];
                ldsm4(a, aAdr1 + kb);
#pragma unroll
                for (int P = 0; P < 4; ++P) ldsm4(bb[P], bAdr1[P] + kb);
#pragma unroll
                for (int P = 0; P < 4; ++P)
#pragma unroll
                    for (int s = 0; s < 2; ++s)
                        mma16816h(c1[2 * P + s], a, bb[P] + 2 * s);
            }
            int jA = wid * 16 + r;
            float b0A = smf[SM_B0 / 4 + jA], b0B = smf[SM_B0 / 4 + jA + 8];
            int q = lane & 3;
#pragma unroll
            for (int nt = 0; nt < 8; ++nt) {
                float v0 = silu_f(c1[nt][0] + b0A);
                float v1 = silu_f(c1[nt][1] + b0A);
                float v2 = silu_f(c1[nt][2] + b0B);
                float v3 = silu_f(c1[nt][3] + b0B);
                __half2 hA = __floats2half2_rn(v0, v1);
                __half2 hB = __floats2half2_rn(v2, v3);
                *(u32*)(smem + SM_S + jA * 144 + (nt * 4 + q) * 4) = *(u32*)&hA;
                *(u32*)(smem + SM_S + (jA + 8) * 144 + (nt * 4 + q) * 4) = *(u32*)&hB;
            }
        }
        __syncthreads();

        // ---- phase 2 mma: warp = 16j x 32p, K=256, B via ldmatrix.trans ----
        float c[4][4];
#pragma unroll
        for (int nt = 0; nt < 4; ++nt)
#pragma unroll
            for (int e = 0; e < 4; ++e) c[nt][e] = 0.0f;
#pragma unroll 4
        for (int kt = 0; kt < 16; ++kt) {
            u32 a[4], bt[2][4];
            ldsm4(a, aAdr2 + kt * 32);
            ldsm4t(bt[0], bAdr2[0] + kt * 16 * 144);
            ldsm4t(bt[1], bAdr2[1] + kt * 16 * 144);
#pragma unroll
            for (int P = 0; P < 2; ++P)
#pragma unroll
                for (int s = 0; s < 2; ++s)
                    mma16816h(c[2 * P + s], a, bt[P] + 2 * s);
        }

        // ---- epilogue: silu + w2, reduce over j (16-warp form) ----
        float pacc[8];
#pragma unroll
        for (int e = 0; e < 8; ++e) pacc[e] = 0.0f;
        {
            int jA = mg * 16 + r;
            float b1A = smf[SM_SB1 / 4 + jA],     w2A = smf[SM_SW2 / 4 + jA];
            float b1B = smf[SM_SB1 / 4 + jA + 8], w2B = smf[SM_SW2 / 4 + jA + 8];
#pragma unroll
            for (int nt = 0; nt < 4; ++nt) {
                float* cc = c[nt];
                pacc[nt * 2 + 0] += w2A * silu_f(cc[0] + b1A) + w2B * silu_f(cc[2] + b1B);
                pacc[nt * 2 + 1] += w2A * silu_f(cc[1] + b1A) + w2B * silu_f(cc[3] + b1B);
            }
        }
#pragma unroll
        for (int e = 0; e < 8; ++e) {
            pacc[e] += __shfl_xor_sync(0xffffffffu, pacc[e], 16);
            pacc[e] += __shfl_xor_sync(0xffffffffu, pacc[e], 8);
            pacc[e] += __shfl_xor_sync(0xffffffffu, pacc[e], 4);
        }
        if (lane < 4) {
#pragma unroll
            for (int e = 0; e < 8; ++e) {
                int lp = (e >> 1) * 8 + lane * 2 + (e & 1);
                smf[SM_RED / 4 + wid * 36 + lp] = pacc[e];
            }
        }
        __syncthreads();
        if (tid < 64) {
            int p = tid, ngx = p >> 5, lp = p & 31;
            float s = bias2;
#pragma unroll
            for (int m = 0; m < 8; ++m)
                s += smf[SM_RED / 4 + (m * 2 + ngx) * 36 + lp];
            out[(size_t)b * NPTS + p0 + p] = s;
        }
        __syncthreads();
    }
}

// ---------------- launch -----------------------------------------------------
extern "C" void kernel_launch(void* const* d_in, const int* in_sizes, int n_in,
                              void* d_out, int out_size) {
    const float* x   = (const float*)d_in[0];
    const float* sdf = (const float*)d_in[1];
    HP hp;
    hp.pw[0]  = (const float*)d_in[2];  hp.pw[1]  = (const float*)d_in[7];
    hp.pw[2]  = (const float*)d_in[12]; hp.pw[3]  = (const float*)d_in[17];
    hp.pb[0]  = (const float*)d_in[3];  hp.pb[1]  = (const float*)d_in[8];
    hp.pb[2]  = (const float*)d_in[13]; hp.pb[3]  = (const float*)d_in[18];
    hp.lnw[0] = (const float*)d_in[4];  hp.lnw[1] = (const float*)d_in[9];
    hp.lnw[2] = (const float*)d_in[14]; hp.lnw[3] = (const float*)d_in[19];
    hp.lnb[0] = (const float*)d_in[5];  hp.lnb[1] = (const float*)d_in[10];
    hp.lnb[2] = (const float*)d_in[15]; hp.lnb[3] = (const float*)d_in[20];
    const float* bias[4] = {(const float*)d_in[6],  (const float*)d_in[11],
                            (const float*)d_in[16], (const float*)d_in[21]};
    const float* mw0 = (const float*)d_in[22];
    const float* mb0 = (const float*)d_in[23];
    const float* mw1 = (const float*)d_in[24];
    const float* mb1 = (const float*)d_in[25];
    const float* mw2 = (const float*)d_in[26];
    const float* mb2 = (const float*)d_in[27];
    float* out = (float*)d_out;

    cudaFuncSetAttribute(mlp_kernel, cudaFuncAttributeMaxDynamicSharedMemorySize,
                         K3_SMEM_BYTES);

    enc_kernel<<<NPTS / 256, 256>>>(x);
    hyperw_kernel<<<NB * 4, 256>>>(sdf, hp);

    dim3 g2(NPTS / 256, NB);
    hyper_apply_kernel<<<g2, 256>>>(bias[0], bias[1], bias[2], bias[3]);

    mlp_kernel<<<MLP_BLOCKS, MLP_THREADS, K3_SMEM_BYTES>>>(mw0, mb0, mw1, mb1,
                                                           mw2, mb2, out);
}